// round 1
// baseline (speedup 1.0000x reference)
#include <cuda_runtime.h>
#include <cuda_bf16.h>

#define NNODES 100000
#define DIM 128

// Scratch (device globals: no allocation allowed in kernel_launch)
__device__ float g_agg[NNODES * DIM];   // (1+eps)*x + scatter-add target
__device__ float g_h1[NNODES * DIM];    // relu(h @ W1 + b1)
__device__ int   g_is64;                // edge_index dtype flag

// ---------------------------------------------------------------------------
// Detect whether edge_index is int64 or int32.
// For int64 non-negative node ids (< 2^31), every odd 32-bit word is zero.
// For int32 random ids in [0, 1e5), 128 consecutive zeros is impossible.
// ---------------------------------------------------------------------------
__global__ void detect_kernel(const unsigned int* __restrict__ w) {
    if (threadIdx.x == 0 && blockIdx.x == 0) {
        int allzero = 1;
        for (int i = 1; i < 256; i += 2) {
            if (w[i] != 0u) { allzero = 0; break; }
        }
        g_is64 = allzero;
    }
}

// ---------------------------------------------------------------------------
// agg[i] = (1 + eps) * x[i]   (fused residual init; overwritten each replay)
// ---------------------------------------------------------------------------
__global__ void init_kernel(const float4* __restrict__ x,
                            const float* __restrict__ eps, int n4) {
    float s = 1.0f + eps[0];
    float4* agg = (float4*)g_agg;
    int i = blockIdx.x * blockDim.x + threadIdx.x;
    int stride = gridDim.x * blockDim.x;
    for (; i < n4; i += stride) {
        float4 v = x[i];
        v.x *= s; v.y *= s; v.z *= s; v.w *= s;
        agg[i] = v;
    }
}

// ---------------------------------------------------------------------------
// Scatter-add: one warp per edge; each lane moves 4 floats (float4 gather +
// red.global.add.v4.f32, a single 16B L2 reduction per lane).
// ---------------------------------------------------------------------------
__global__ void scatter_kernel(const float4* __restrict__ x,
                               const void* __restrict__ ei, int E) {
    int t = blockIdx.x * blockDim.x + threadIdx.x;
    int e = t >> 5;
    if (e >= E) return;
    int lane = t & 31;

    long long src, dst;
    if (g_is64) {
        const long long* p = (const long long*)ei;
        src = p[e];
        dst = p[E + e];
    } else {
        const int* p = (const int*)ei;
        src = p[e];
        dst = p[E + e];
    }

    float4 v = x[src * 32 + lane];
    float* q = g_agg + dst * 128 + lane * 4;
    asm volatile("red.global.add.v4.f32 [%0], {%1,%2,%3,%4};"
                 :: "l"(q), "f"(v.x), "f"(v.y), "f"(v.z), "f"(v.w)
                 : "memory");
}

// ---------------------------------------------------------------------------
// C[n,128] = A[n,128] @ W[128,128] + bias, optional ReLU.
// 128 threads/block (one output column each), 16 rows/block.
// W resident in shared (64 KB); A-tile reads are float4 broadcasts.
// ---------------------------------------------------------------------------
template <int RELU>
__global__ void gemm_kernel(const float* __restrict__ A,
                            const float* __restrict__ W,
                            const float* __restrict__ bias,
                            float* __restrict__ C, int n) {
    extern __shared__ float smem[];
    float* Wsh = smem;             // 128*128
    float* Ash = smem + 128 * 128; // 16*128
    const int RB = 16;
    int col = threadIdx.x;

    for (int i = col; i < 128 * 128; i += 128) Wsh[i] = W[i];

    int row0 = blockIdx.x * RB;
    for (int r = 0; r < RB; r++) {
        int row = row0 + r;
        Ash[r * 128 + col] = (row < n) ? A[row * 128 + col] : 0.0f;
    }
    __syncthreads();

    float b = bias[col];
    float acc[RB];
#pragma unroll
    for (int r = 0; r < RB; r++) acc[r] = b;

#pragma unroll 2
    for (int k = 0; k < 128; k += 4) {
        float w0 = Wsh[(k + 0) * 128 + col];
        float w1 = Wsh[(k + 1) * 128 + col];
        float w2 = Wsh[(k + 2) * 128 + col];
        float w3 = Wsh[(k + 3) * 128 + col];
#pragma unroll
        for (int r = 0; r < RB; r++) {
            float4 a = *(const float4*)&Ash[r * 128 + k];
            acc[r] = fmaf(a.x, w0, acc[r]);
            acc[r] = fmaf(a.y, w1, acc[r]);
            acc[r] = fmaf(a.z, w2, acc[r]);
            acc[r] = fmaf(a.w, w3, acc[r]);
        }
    }

    for (int r = 0; r < RB; r++) {
        int row = row0 + r;
        if (row < n) {
            float v = acc[r];
            if (RELU) v = fmaxf(v, 0.0f);
            C[row * 128 + col] = v;
        }
    }
}

// ---------------------------------------------------------------------------
extern "C" void kernel_launch(void* const* d_in, const int* in_sizes, int n_in,
                              void* d_out, int out_size) {
    const float* x   = (const float*)d_in[0];
    const void*  ei  = d_in[1];
    const float* W1  = (const float*)d_in[2];
    const float* b1  = (const float*)d_in[3];
    const float* W2  = (const float*)d_in[4];
    const float* b2  = (const float*)d_in[5];
    const float* eps = (const float*)d_in[6];

    int N = in_sizes[0] / DIM;
    int E = in_sizes[1] / 2;

    float* agg_ptr = nullptr;
    float* h1_ptr  = nullptr;
    cudaGetSymbolAddress((void**)&agg_ptr, g_agg);
    cudaGetSymbolAddress((void**)&h1_ptr,  g_h1);

    detect_kernel<<<1, 32>>>((const unsigned int*)ei);

    int n4 = N * (DIM / 4);
    init_kernel<<<(n4 + 255) / 256, 256>>>((const float4*)x, eps, n4);

    long long tot = (long long)E * 32;
    scatter_kernel<<<(int)((tot + 255) / 256), 256>>>((const float4*)x, ei, E);

    size_t smem = (128 * 128 + 16 * 128) * sizeof(float);  // 72 KB
    cudaFuncSetAttribute(gemm_kernel<1>,
                         cudaFuncAttributeMaxDynamicSharedMemorySize, (int)smem);
    cudaFuncSetAttribute(gemm_kernel<0>,
                         cudaFuncAttributeMaxDynamicSharedMemorySize, (int)smem);

    int nb = (N + 15) / 16;
    gemm_kernel<1><<<nb, 128, smem>>>(agg_ptr, W1, b1, h1_ptr, N);
    gemm_kernel<0><<<nb, 128, smem>>>(h1_ptr, W2, b2, (float*)d_out, N);
}

// round 3
// speedup vs baseline: 1.6106x; 1.6106x over previous
#include <cuda_runtime.h>
#include <cuda_bf16.h>
#include <cstdint>

#define NNODES 100000
#define DIM 128

// ---------------------------------------------------------------------------
// Device-global scratch (no allocations allowed anywhere)
// ---------------------------------------------------------------------------
__device__ float g_agg[NNODES * DIM];   // (1+eps)*x + scatter-add target
__device__ float g_h1[NNODES * DIM];    // relu(h @ W1 + b1)
__device__ int   g_is64;                // edge_index dtype flag

// ---------------------------------------------------------------------------
// Packed f32x2 helpers (family-level sm_100+ PTX; NOT arch-specific)
// ---------------------------------------------------------------------------
typedef unsigned long long u64;

__device__ __forceinline__ u64 pack2(float lo, float hi) {
    u64 r;
    asm("mov.b64 %0, {%1, %2};" : "=l"(r) : "f"(lo), "f"(hi));
    return r;
}
__device__ __forceinline__ void unpack2(u64 v, float& lo, float& hi) {
    asm("mov.b64 {%0, %1}, %2;" : "=f"(lo), "=f"(hi) : "l"(v));
}
__device__ __forceinline__ u64 ffma2(u64 a, u64 b, u64 c) {
    u64 d;
    asm("fma.rn.f32x2 %0, %1, %2, %3;" : "=l"(d) : "l"(a), "l"(b), "l"(c));
    return d;
}

// ---------------------------------------------------------------------------
// edge_index dtype detection (int64 ids < 2^31 -> odd words all zero)
// ---------------------------------------------------------------------------
__global__ void detect_kernel(const unsigned int* __restrict__ w) {
    if (threadIdx.x == 0 && blockIdx.x == 0) {
        int allzero = 1;
        for (int i = 1; i < 256; i += 2)
            if (w[i] != 0u) { allzero = 0; break; }
        g_is64 = allzero;
    }
}

// ---------------------------------------------------------------------------
// agg[i] = (1 + eps) * x[i]
// ---------------------------------------------------------------------------
__global__ void init_kernel(const float4* __restrict__ x,
                            const float* __restrict__ eps, int n4) {
    float s = 1.0f + eps[0];
    float4* agg = (float4*)g_agg;
    int i = blockIdx.x * blockDim.x + threadIdx.x;
    int stride = gridDim.x * blockDim.x;
    for (; i < n4; i += stride) {
        float4 v = x[i];
        v.x *= s; v.y *= s; v.z *= s; v.w *= s;
        agg[i] = v;
    }
}

// ---------------------------------------------------------------------------
// Scatter-add: one warp per edge, red.global.add.v4.f32 per lane.
// ---------------------------------------------------------------------------
__global__ void scatter_kernel(const float4* __restrict__ x,
                               const void* __restrict__ ei, int E) {
    int t = blockIdx.x * blockDim.x + threadIdx.x;
    int e = t >> 5;
    if (e >= E) return;
    int lane = t & 31;

    long long src, dst;
    if (g_is64) {
        const long long* p = (const long long*)ei;
        src = p[e];
        dst = p[E + e];
    } else {
        const int* p = (const int*)ei;
        src = p[e];
        dst = p[E + e];
    }

    float4 v = x[src * 32 + lane];
    float* q = g_agg + dst * 128 + lane * 4;
    asm volatile("red.global.add.v4.f32 [%0], {%1,%2,%3,%4};"
                 :: "l"(q), "f"(v.x), "f"(v.y), "f"(v.z), "f"(v.w)
                 : "memory");
}

// ---------------------------------------------------------------------------
// GEMM: C[n,128] = A[n,128] @ W[128,128] + bias (optional ReLU).
// 256 threads/CTA, one 128x128 tile per CTA.
// Thread (tx, ty): rows ty*8..+7, cols tx*8..+7 -> 8x4 packed f32x2 accums.
// W kept in natural [K][N] layout (adjacent N pairs pack into f32x2).
// Smem: W 64KB + A-tile 64KB = 128KB.
// ---------------------------------------------------------------------------
template <int RELU>
__global__ void __launch_bounds__(256, 1)
gemm_f32x2_kernel(const float* __restrict__ A, const float* __restrict__ W,
                  const float* __restrict__ bias, float* __restrict__ C,
                  int n) {
    extern __shared__ float smem[];
    float*  Wsh  = smem;           // 128*128
    float*  Ash  = smem + 16384;   // 128*128
    float4* Wsh4 = (float4*)Wsh;
    float4* Ash4 = (float4*)Ash;

    int tid = threadIdx.x;
    int tx = tid & 15;      // column block: cols tx*8 .. tx*8+7
    int ty = tid >> 4;      // row block:    rows ty*8 .. ty*8+7
    int row0 = blockIdx.x << 7;

    // Stage W (coalesced float4)
    const float4* W4 = (const float4*)W;
#pragma unroll
    for (int i = 0; i < 16; i++) Wsh4[tid + 256 * i] = W4[tid + 256 * i];

    // Stage A tile (coalesced float4, zero-pad tail rows)
    const float4* A4 = (const float4*)A;
#pragma unroll
    for (int i = 0; i < 16; i++) {
        int idx = tid + 256 * i;      // float4 index in 128x32 tile
        int r = idx >> 5;
        int gr = row0 + r;
        Ash4[idx] = (gr < n) ? A4[(size_t)gr * 32 + (idx & 31)]
                             : make_float4(0.f, 0.f, 0.f, 0.f);
    }
    __syncthreads();

    // Accumulators, initialized with bias
    u64 acc[8][4];
#pragma unroll
    for (int p = 0; p < 4; p++) {
        u64 b = pack2(bias[tx * 8 + 2 * p], bias[tx * 8 + 2 * p + 1]);
#pragma unroll
        for (int r = 0; r < 8; r++) acc[r][p] = b;
    }

#pragma unroll 4
    for (int k = 0; k < 128; k++) {
        float4 w0 = Wsh4[k * 32 + tx * 2];
        float4 w1 = Wsh4[k * 32 + tx * 2 + 1];
        u64 wp0 = pack2(w0.x, w0.y);
        u64 wp1 = pack2(w0.z, w0.w);
        u64 wp2 = pack2(w1.x, w1.y);
        u64 wp3 = pack2(w1.z, w1.w);
#pragma unroll
        for (int r = 0; r < 8; r++) {
            float a = Ash[(ty * 8 + r) * 128 + k];
            u64 a2 = pack2(a, a);
            acc[r][0] = ffma2(a2, wp0, acc[r][0]);
            acc[r][1] = ffma2(a2, wp1, acc[r][1]);
            acc[r][2] = ffma2(a2, wp2, acc[r][2]);
            acc[r][3] = ffma2(a2, wp3, acc[r][3]);
        }
    }

    // Epilogue: unpack, ReLU, vectorized store
#pragma unroll
    for (int r = 0; r < 8; r++) {
        int gr = row0 + ty * 8 + r;
        if (gr < n) {
            float o[8];
#pragma unroll
            for (int p = 0; p < 4; p++) {
                unpack2(acc[r][p], o[2 * p], o[2 * p + 1]);
                if (RELU) {
                    o[2 * p]     = fmaxf(o[2 * p], 0.0f);
                    o[2 * p + 1] = fmaxf(o[2 * p + 1], 0.0f);
                }
            }
            float4* dst = (float4*)(C + (size_t)gr * 128 + tx * 8);
            dst[0] = make_float4(o[0], o[1], o[2], o[3]);
            dst[1] = make_float4(o[4], o[5], o[6], o[7]);
        }
    }
}

// ---------------------------------------------------------------------------
extern "C" void kernel_launch(void* const* d_in, const int* in_sizes, int n_in,
                              void* d_out, int out_size) {
    const float* x   = (const float*)d_in[0];
    const void*  ei  = d_in[1];
    const float* W1  = (const float*)d_in[2];
    const float* b1  = (const float*)d_in[3];
    const float* W2  = (const float*)d_in[4];
    const float* b2  = (const float*)d_in[5];
    const float* eps = (const float*)d_in[6];

    int N = in_sizes[0] / DIM;
    int E = in_sizes[1] / 2;

    float* agg_ptr = nullptr;
    float* h1_ptr  = nullptr;
    cudaGetSymbolAddress((void**)&agg_ptr, g_agg);
    cudaGetSymbolAddress((void**)&h1_ptr,  g_h1);

    detect_kernel<<<1, 32>>>((const unsigned int*)ei);

    int n4 = N * (DIM / 4);
    init_kernel<<<(n4 + 255) / 256, 256>>>((const float4*)x, eps, n4);

    long long tot = (long long)E * 32;
    scatter_kernel<<<(int)((tot + 255) / 256), 256>>>((const float4*)x, ei, E);

    const int SMEM_GEMM = 2 * 128 * 128 * sizeof(float);  // 131072
    cudaFuncSetAttribute(gemm_f32x2_kernel<1>,
                         cudaFuncAttributeMaxDynamicSharedMemorySize, SMEM_GEMM);
    cudaFuncSetAttribute(gemm_f32x2_kernel<0>,
                         cudaFuncAttributeMaxDynamicSharedMemorySize, SMEM_GEMM);

    int nb = (N + 127) / 128;
    gemm_f32x2_kernel<1><<<nb, 256, SMEM_GEMM>>>(agg_ptr, W1, b1, h1_ptr, N);
    gemm_f32x2_kernel<0><<<nb, 256, SMEM_GEMM>>>(h1_ptr, W2, b2, (float*)d_out, N);
}

// round 4
// speedup vs baseline: 2.0896x; 1.2974x over previous
#include <cuda_runtime.h>
#include <cuda_bf16.h>
#include <cstdint>

#define NNODES 100000
#define DIM 128

// ---------------------------------------------------------------------------
// Device-global scratch (no allocations allowed anywhere)
// ---------------------------------------------------------------------------
__device__ float g_agg[NNODES * DIM];   // (1+eps)*x + scatter-add target
__device__ float g_h1[NNODES * DIM];    // relu(h @ W1 + b1)
__device__ int   g_is64;                // edge_index dtype flag
__device__ __nv_bfloat16 g_wt1_hi[DIM * DIM];  // W1^T split to bf16 hi/lo
__device__ __nv_bfloat16 g_wt1_lo[DIM * DIM];
__device__ __nv_bfloat16 g_wt2_hi[DIM * DIM];
__device__ __nv_bfloat16 g_wt2_lo[DIM * DIM];

// ---------------------------------------------------------------------------
// helpers
// ---------------------------------------------------------------------------
__device__ __forceinline__ uint32_t smem_u32(const void* p) {
    uint32_t a;
    asm("{ .reg .u64 t; cvta.to.shared.u64 t, %1; cvt.u32.u64 %0, t; }"
        : "=r"(a) : "l"(p));
    return a;
}

__device__ __forceinline__ void ldsm4(uint32_t* r, uint32_t addr) {
    asm volatile("ldmatrix.sync.aligned.m8n8.x4.shared.b16 {%0,%1,%2,%3}, [%4];"
                 : "=r"(r[0]), "=r"(r[1]), "=r"(r[2]), "=r"(r[3]) : "r"(addr));
}

__device__ __forceinline__ void mma_bf16(float* d, const uint32_t* a,
                                         uint32_t b0, uint32_t b1) {
    asm volatile(
        "mma.sync.aligned.m16n8k16.row.col.f32.bf16.bf16.f32 "
        "{%0,%1,%2,%3}, {%4,%5,%6,%7}, {%8,%9}, {%0,%1,%2,%3};"
        : "+f"(d[0]), "+f"(d[1]), "+f"(d[2]), "+f"(d[3])
        : "r"(a[0]), "r"(a[1]), "r"(a[2]), "r"(a[3]), "r"(b0), "r"(b1));
}

// ---------------------------------------------------------------------------
// edge_index dtype detection (int64 ids < 2^31 -> odd words all zero)
// ---------------------------------------------------------------------------
__global__ void detect_kernel(const unsigned int* __restrict__ w) {
    if (threadIdx.x == 0 && blockIdx.x == 0) {
        int allzero = 1;
        for (int i = 1; i < 256; i += 2)
            if (w[i] != 0u) { allzero = 0; break; }
        g_is64 = allzero;
    }
}

// ---------------------------------------------------------------------------
// agg[i] = (1 + eps) * x[i]
// ---------------------------------------------------------------------------
__global__ void init_kernel(const float4* __restrict__ x,
                            const float* __restrict__ eps, int n4) {
    float s = 1.0f + eps[0];
    float4* agg = (float4*)g_agg;
    int i = blockIdx.x * blockDim.x + threadIdx.x;
    int stride = gridDim.x * blockDim.x;
    for (; i < n4; i += stride) {
        float4 v = x[i];
        v.x *= s; v.y *= s; v.z *= s; v.w *= s;
        agg[i] = v;
    }
}

// ---------------------------------------------------------------------------
// Scatter-add: one warp per edge, red.global.add.v4.f32 per lane.
// ---------------------------------------------------------------------------
__global__ void scatter_kernel(const float4* __restrict__ x,
                               const void* __restrict__ ei, int E) {
    int t = blockIdx.x * blockDim.x + threadIdx.x;
    int e = t >> 5;
    if (e >= E) return;
    int lane = t & 31;

    long long src, dst;
    if (g_is64) {
        const long long* p = (const long long*)ei;
        src = p[e];
        dst = p[E + e];
    } else {
        const int* p = (const int*)ei;
        src = p[e];
        dst = p[E + e];
    }

    float4 v = x[src * 32 + lane];
    float* q = g_agg + dst * 128 + lane * 4;
    asm volatile("red.global.add.v4.f32 [%0], {%1,%2,%3,%4};"
                 :: "l"(q), "f"(v.x), "f"(v.y), "f"(v.z), "f"(v.w)
                 : "memory");
}

// ---------------------------------------------------------------------------
// Weight prep: Wt[n][k] = W[k][n], split fp32 -> bf16 hi + lo.
// ---------------------------------------------------------------------------
__global__ void prep_w_kernel(const float* __restrict__ W1,
                              const float* __restrict__ W2) {
    int i = blockIdx.x * blockDim.x + threadIdx.x;
    if (i >= 2 * DIM * DIM) return;
    const float* W = (i < DIM * DIM) ? W1 : W2;
    __nv_bfloat16* H = (i < DIM * DIM) ? g_wt1_hi : g_wt2_hi;
    __nv_bfloat16* L = (i < DIM * DIM) ? g_wt1_lo : g_wt2_lo;
    int j = i & (DIM * DIM - 1);
    int nIdx = j >> 7;
    int k = j & 127;
    float w = W[k * DIM + nIdx];
    __nv_bfloat16 h = __float2bfloat16(w);
    H[j] = h;
    L[j] = __float2bfloat16(w - __bfloat162float(h));
}

// ---------------------------------------------------------------------------
// Tensor-core GEMM via mma.sync (family-level PTX, no "a" features).
// C[n,128] = A[n,128] @ W[128,128] + bias, optional ReLU.
// CTA: 256 rows x 128 cols; 8 warps x 32 rows. bf16 hi/lo 3-pass for fp32
// accuracy: D = Ah*Bh + Ah*Bl + Al*Bh.
// Smem rows padded to 136 bf16 (272B = 17*16B -> conflict-free ldmatrix).
// ---------------------------------------------------------------------------
#define PADB 272                       // padded row stride in bytes
#define SM_AH 0                        // 256*272 = 69632
#define SM_AL 69632                    // 256*272
#define SM_BH 139264                   // 128*272 = 34816
#define SM_BL 174080
#define SMEM_GEMM_BYTES 208896

__global__ void __launch_bounds__(256, 1)
gemm_mma_kernel(const float* __restrict__ A,
                const __nv_bfloat16* __restrict__ Bh,
                const __nv_bfloat16* __restrict__ Bl,
                const float* __restrict__ bias,
                float* __restrict__ C, int n, int relu) {
    extern __shared__ char smem[];
    uint32_t sb = smem_u32(smem);
    int tid = threadIdx.x, wid = tid >> 5, lane = tid & 31;
    int row0 = blockIdx.x * 256;

    // ---- Stage A: fp32 -> bf16 hi/lo into padded smem ----
    const float4* A4 = (const float4*)A;
#pragma unroll
    for (int i = 0; i < 32; i++) {
        int idx = tid + 256 * i;          // float4 index in 256x32 grid
        int r = idx >> 5, c4 = idx & 31;  // c4: which float4 in row
        int gr = row0 + r;
        float4 v = (gr < n) ? A4[(size_t)gr * 32 + c4]
                            : make_float4(0.f, 0.f, 0.f, 0.f);
        __nv_bfloat16 h0 = __float2bfloat16(v.x);
        __nv_bfloat16 h1 = __float2bfloat16(v.y);
        __nv_bfloat16 h2 = __float2bfloat16(v.z);
        __nv_bfloat16 h3 = __float2bfloat16(v.w);
        __nv_bfloat162 ph0 = __halves2bfloat162(h0, h1);
        __nv_bfloat162 ph1 = __halves2bfloat162(h2, h3);
        __nv_bfloat162 pl0 = __halves2bfloat162(
            __float2bfloat16(v.x - __bfloat162float(h0)),
            __float2bfloat16(v.y - __bfloat162float(h1)));
        __nv_bfloat162 pl1 = __halves2bfloat162(
            __float2bfloat16(v.z - __bfloat162float(h2)),
            __float2bfloat16(v.w - __bfloat162float(h3)));
        char* ph = smem + SM_AH + r * PADB + c4 * 8;
        char* pl = smem + SM_AL + r * PADB + c4 * 8;
        *(uint2*)ph = make_uint2(*reinterpret_cast<uint32_t*>(&ph0),
                                 *reinterpret_cast<uint32_t*>(&ph1));
        *(uint2*)pl = make_uint2(*reinterpret_cast<uint32_t*>(&pl0),
                                 *reinterpret_cast<uint32_t*>(&pl1));
    }

    // ---- Stage B (Wt hi/lo) into padded smem ----
    const uint2* bh2 = (const uint2*)Bh;
    const uint2* bl2 = (const uint2*)Bl;
#pragma unroll
    for (int i = 0; i < 16; i++) {
        int idx = tid + 256 * i;          // uint2 (4 bf16) index in 128x32 grid
        int r = idx >> 5, c4 = idx & 31;
        *(uint2*)(smem + SM_BH + r * PADB + c4 * 8) = bh2[idx];
        *(uint2*)(smem + SM_BL + r * PADB + c4 * 8) = bl2[idx];
    }
    __syncthreads();

    // ---- Per-lane ldmatrix base offsets ----
    int lr = lane & 7;        // row within 8x8 tile
    int li = lane >> 3;       // which of the 4 tiles
    // A x4 tiles: (r+0,k+0)(r+8,k+0)(r+0,k+8)(r+8,k+8)
    uint32_t aoff = (uint32_t)((wid * 32 + lr + (li & 1) * 8) * PADB +
                               ((li >> 1) * 8) * 2);
    // B x4 tiles: (n+0,k+0)(n+0,k+8)(n+8,k+0)(n+8,k+8)
    uint32_t boff = (uint32_t)((lr + (li >> 1) * 8) * PADB + ((li & 1) * 8) * 2);

    float acc[2][16][4];
#pragma unroll
    for (int mt = 0; mt < 2; mt++)
#pragma unroll
        for (int nt = 0; nt < 16; nt++)
#pragma unroll
            for (int q = 0; q < 4; q++) acc[mt][nt][q] = 0.0f;

    for (int ks = 0; ks < 8; ks++) {
        uint32_t kadd = ks * 32;  // 16 bf16 = 32 bytes per k-step
        uint32_t ah[2][4], al[2][4];
        ldsm4(ah[0], sb + SM_AH + aoff + kadd);
        ldsm4(ah[1], sb + SM_AH + aoff + 16 * PADB + kadd);
        ldsm4(al[0], sb + SM_AL + aoff + kadd);
        ldsm4(al[1], sb + SM_AL + aoff + 16 * PADB + kadd);
#pragma unroll
        for (int ng = 0; ng < 8; ng++) {
            uint32_t nadd = ng * 16 * PADB;
            uint32_t bh[4], bl[4];
            ldsm4(bh, sb + SM_BH + boff + nadd + kadd);
            ldsm4(bl, sb + SM_BL + boff + nadd + kadd);
#pragma unroll
            for (int mt = 0; mt < 2; mt++) {
                mma_bf16(acc[mt][2 * ng],     ah[mt], bh[0], bh[1]);
                mma_bf16(acc[mt][2 * ng],     ah[mt], bl[0], bl[1]);
                mma_bf16(acc[mt][2 * ng],     al[mt], bh[0], bh[1]);
                mma_bf16(acc[mt][2 * ng + 1], ah[mt], bh[2], bh[3]);
                mma_bf16(acc[mt][2 * ng + 1], ah[mt], bl[2], bl[3]);
                mma_bf16(acc[mt][2 * ng + 1], al[mt], bh[2], bh[3]);
            }
        }
    }

    // ---- Epilogue: bias + ReLU, st.v2 per fragment half ----
#pragma unroll
    for (int nt = 0; nt < 16; nt++) {
        int col = nt * 8 + (lane & 3) * 2;
        float2 bv = *(const float2*)(bias + col);
#pragma unroll
        for (int mt = 0; mt < 2; mt++) {
            int r0 = row0 + wid * 32 + mt * 16 + (lane >> 2);
            float* a = acc[mt][nt];
            float v0 = a[0] + bv.x, v1 = a[1] + bv.y;
            float v2 = a[2] + bv.x, v3 = a[3] + bv.y;
            if (relu) {
                v0 = fmaxf(v0, 0.f); v1 = fmaxf(v1, 0.f);
                v2 = fmaxf(v2, 0.f); v3 = fmaxf(v3, 0.f);
            }
            if (r0 < n)     *(float2*)(C + (size_t)r0 * 128 + col) = make_float2(v0, v1);
            if (r0 + 8 < n) *(float2*)(C + (size_t)(r0 + 8) * 128 + col) = make_float2(v2, v3);
        }
    }
}

// ---------------------------------------------------------------------------
extern "C" void kernel_launch(void* const* d_in, const int* in_sizes, int n_in,
                              void* d_out, int out_size) {
    const float* x   = (const float*)d_in[0];
    const void*  ei  = d_in[1];
    const float* W1  = (const float*)d_in[2];
    const float* b1  = (const float*)d_in[3];
    const float* W2  = (const float*)d_in[4];
    const float* b2  = (const float*)d_in[5];
    const float* eps = (const float*)d_in[6];

    int N = in_sizes[0] / DIM;
    int E = in_sizes[1] / 2;

    float* agg_ptr = nullptr;
    float* h1_ptr  = nullptr;
    __nv_bfloat16 *wt1h, *wt1l, *wt2h, *wt2l;
    cudaGetSymbolAddress((void**)&agg_ptr, g_agg);
    cudaGetSymbolAddress((void**)&h1_ptr,  g_h1);
    cudaGetSymbolAddress((void**)&wt1h, g_wt1_hi);
    cudaGetSymbolAddress((void**)&wt1l, g_wt1_lo);
    cudaGetSymbolAddress((void**)&wt2h, g_wt2_hi);
    cudaGetSymbolAddress((void**)&wt2l, g_wt2_lo);

    detect_kernel<<<1, 32>>>((const unsigned int*)ei);
    prep_w_kernel<<<(2 * DIM * DIM + 255) / 256, 256>>>(W1, W2);

    int n4 = N * (DIM / 4);
    init_kernel<<<(n4 + 255) / 256, 256>>>((const float4*)x, eps, n4);

    long long tot = (long long)E * 32;
    scatter_kernel<<<(int)((tot + 255) / 256), 256>>>((const float4*)x, ei, E);

    cudaFuncSetAttribute(gemm_mma_kernel,
                         cudaFuncAttributeMaxDynamicSharedMemorySize,
                         SMEM_GEMM_BYTES);

    int nb = (N + 255) / 256;
    gemm_mma_kernel<<<nb, 256, SMEM_GEMM_BYTES>>>(agg_ptr, wt1h, wt1l, b1,
                                                  h1_ptr, N, 1);
    gemm_mma_kernel<<<nb, 256, SMEM_GEMM_BYTES>>>(h1_ptr, wt2h, wt2l, b2,
                                                  (float*)d_out, N, 0);
}

// round 5
// speedup vs baseline: 3.3876x; 1.6211x over previous
#include <cuda_runtime.h>
#include <cuda_bf16.h>
#include <cstdint>

#define NNODES 100000
#define EDGES_MAX 1600000
#define DIM 128
#define SCAN_BLK 4096
#define NB_SCAN ((NNODES + SCAN_BLK - 1) / SCAN_BLK)

// ---------------------------------------------------------------------------
// Device-global scratch (no allocations allowed anywhere)
// ---------------------------------------------------------------------------
__device__ float g_agg[NNODES * DIM];
__device__ float g_h1[NNODES * DIM];
__device__ int   g_is64;
__device__ __nv_bfloat16 g_wt1_hi[DIM * DIM];
__device__ __nv_bfloat16 g_wt1_lo[DIM * DIM];
__device__ __nv_bfloat16 g_wt2_hi[DIM * DIM];
__device__ __nv_bfloat16 g_wt2_lo[DIM * DIM];
// CSR build
__device__ int g_cnt[NNODES];
__device__ int g_rowptr[NNODES + 1];
__device__ int g_cur[NNODES];
__device__ int g_blksum[NB_SCAN + 1];
__device__ int g_esrc[EDGES_MAX];

// ---------------------------------------------------------------------------
// helpers
// ---------------------------------------------------------------------------
__device__ __forceinline__ uint32_t smem_u32(const void* p) {
    uint32_t a;
    asm("{ .reg .u64 t; cvta.to.shared.u64 t, %1; cvt.u32.u64 %0, t; }"
        : "=r"(a) : "l"(p));
    return a;
}
__device__ __forceinline__ void ldsm4(uint32_t* r, uint32_t addr) {
    asm volatile("ldmatrix.sync.aligned.m8n8.x4.shared.b16 {%0,%1,%2,%3}, [%4];"
                 : "=r"(r[0]), "=r"(r[1]), "=r"(r[2]), "=r"(r[3]) : "r"(addr));
}
__device__ __forceinline__ void mma_bf16(float* d, const uint32_t* a,
                                         uint32_t b0, uint32_t b1) {
    asm volatile(
        "mma.sync.aligned.m16n8k16.row.col.f32.bf16.bf16.f32 "
        "{%0,%1,%2,%3}, {%4,%5,%6,%7}, {%8,%9}, {%0,%1,%2,%3};"
        : "+f"(d[0]), "+f"(d[1]), "+f"(d[2]), "+f"(d[3])
        : "r"(a[0]), "r"(a[1]), "r"(a[2]), "r"(a[3]), "r"(b0), "r"(b1));
}
__device__ __forceinline__ int load_idx(const void* ei, long long pos) {
    return g_is64 ? (int)((const long long*)ei)[pos] : ((const int*)ei)[pos];
}

// ---------------------------------------------------------------------------
// edge_index dtype detection (int64 ids < 2^31 -> odd words all zero)
// ---------------------------------------------------------------------------
__global__ void detect_kernel(const unsigned int* __restrict__ w) {
    if (threadIdx.x == 0 && blockIdx.x == 0) {
        int allzero = 1;
        for (int i = 1; i < 256; i += 2)
            if (w[i] != 0u) { allzero = 0; break; }
        g_is64 = allzero;
    }
}

// ---------------------------------------------------------------------------
// CSR build: zero -> histogram -> 3-phase exclusive scan -> reorder
// ---------------------------------------------------------------------------
__global__ void zero_cnt_kernel(int N) {
    int i = blockIdx.x * blockDim.x + threadIdx.x;
    if (i < N) g_cnt[i] = 0;
}

__global__ void hist_kernel(const void* __restrict__ ei, int E) {
    int i = blockIdx.x * blockDim.x + threadIdx.x;
    if (i < E) atomicAdd(&g_cnt[load_idx(ei, (long long)E + i)], 1);
}

__global__ void scan1_kernel(int N) {  // 512 threads; 4096 elems/block
    __shared__ int sh[512];
    int t = threadIdx.x, b = blockIdx.x;
    int base = b * SCAN_BLK + t * 8;
    int v[8], s = 0;
#pragma unroll
    for (int j = 0; j < 8; j++) {
        int idx = base + j;
        v[j] = (idx < N) ? g_cnt[idx] : 0;
        s += v[j];
    }
    sh[t] = s;
    __syncthreads();
    for (int off = 1; off < 512; off <<= 1) {
        int y = (t >= off) ? sh[t - off] : 0;
        __syncthreads();
        sh[t] += y;
        __syncthreads();
    }
    int run = sh[t] - s;  // exclusive prefix of this thread within block
#pragma unroll
    for (int j = 0; j < 8; j++) {
        int idx = base + j;
        if (idx < N) g_rowptr[idx] = run;
        run += v[j];
    }
    if (t == 511) g_blksum[b] = sh[511];
}

__global__ void scan2_kernel(int nb) {  // 1 thread serial over block sums
    if (threadIdx.x == 0 && blockIdx.x == 0) {
        int acc = 0;
        for (int i = 0; i < nb; i++) {
            int v = g_blksum[i];
            g_blksum[i] = acc;
            acc += v;
        }
    }
}

__global__ void scan3_kernel(int N, int E) {
    int i = blockIdx.x * blockDim.x + threadIdx.x;
    if (i < N) {
        int v = g_rowptr[i] + g_blksum[i / SCAN_BLK];
        g_rowptr[i] = v;
        g_cur[i] = v;
    }
    if (i == 0) g_rowptr[N] = E;
}

__global__ void reorder_kernel(const void* __restrict__ ei, int E) {
    int i = blockIdx.x * blockDim.x + threadIdx.x;
    if (i >= E) return;
    int src = load_idx(ei, i);
    int dst = load_idx(ei, (long long)E + i);
    int pos = atomicAdd(&g_cur[dst], 1);
    g_esrc[pos] = src;
}

// ---------------------------------------------------------------------------
// Aggregation: one warp per node. agg[i] = (1+eps)*x[i] + sum_j x[esrc[j]].
// Regular loads + one store per row; unroll-4 gathers for MLP.
// ---------------------------------------------------------------------------
__global__ void agg_kernel(const float4* __restrict__ x,
                           const float* __restrict__ eps, int N) {
    int w = (blockIdx.x * blockDim.x + threadIdx.x) >> 5;
    if (w >= N) return;
    int lane = threadIdx.x & 31;
    float s = 1.0f + eps[0];

    float4 a = x[(size_t)w * 32 + lane];
    float4 acc = make_float4(a.x * s, a.y * s, a.z * s, a.w * s);

    int j  = g_rowptr[w];
    int r1 = g_rowptr[w + 1];
    for (; j + 4 <= r1; j += 4) {
        int s0 = g_esrc[j],     s1 = g_esrc[j + 1];
        int s2 = g_esrc[j + 2], s3 = g_esrc[j + 3];
        float4 v0 = x[(size_t)s0 * 32 + lane];
        float4 v1 = x[(size_t)s1 * 32 + lane];
        float4 v2 = x[(size_t)s2 * 32 + lane];
        float4 v3 = x[(size_t)s3 * 32 + lane];
        acc.x += v0.x + v1.x + v2.x + v3.x;
        acc.y += v0.y + v1.y + v2.y + v3.y;
        acc.z += v0.z + v1.z + v2.z + v3.z;
        acc.w += v0.w + v1.w + v2.w + v3.w;
    }
    for (; j < r1; j++) {
        float4 v = x[(size_t)g_esrc[j] * 32 + lane];
        acc.x += v.x; acc.y += v.y; acc.z += v.z; acc.w += v.w;
    }
    ((float4*)g_agg)[(size_t)w * 32 + lane] = acc;
}

// ---------------------------------------------------------------------------
// Legacy fallback path (if E > EDGES_MAX): init + atomic scatter
// ---------------------------------------------------------------------------
__global__ void init_kernel(const float4* __restrict__ x,
                            const float* __restrict__ eps, int n4) {
    float s = 1.0f + eps[0];
    float4* agg = (float4*)g_agg;
    int i = blockIdx.x * blockDim.x + threadIdx.x;
    int stride = gridDim.x * blockDim.x;
    for (; i < n4; i += stride) {
        float4 v = x[i];
        v.x *= s; v.y *= s; v.z *= s; v.w *= s;
        agg[i] = v;
    }
}

__global__ void scatter_kernel(const float4* __restrict__ x,
                               const void* __restrict__ ei, int E) {
    int t = blockIdx.x * blockDim.x + threadIdx.x;
    int e = t >> 5;
    if (e >= E) return;
    int lane = t & 31;
    int src = load_idx(ei, e);
    int dst = load_idx(ei, (long long)E + e);
    float4 v = x[(size_t)src * 32 + lane];
    float* q = g_agg + (size_t)dst * 128 + lane * 4;
    asm volatile("red.global.add.v4.f32 [%0], {%1,%2,%3,%4};"
                 :: "l"(q), "f"(v.x), "f"(v.y), "f"(v.z), "f"(v.w)
                 : "memory");
}

// ---------------------------------------------------------------------------
// Weight prep: Wt[n][k] = W[k][n], split fp32 -> bf16 hi + lo.
// ---------------------------------------------------------------------------
__global__ void prep_w_kernel(const float* __restrict__ W1,
                              const float* __restrict__ W2) {
    int i = blockIdx.x * blockDim.x + threadIdx.x;
    if (i >= 2 * DIM * DIM) return;
    const float* W = (i < DIM * DIM) ? W1 : W2;
    __nv_bfloat16* H = (i < DIM * DIM) ? g_wt1_hi : g_wt2_hi;
    __nv_bfloat16* L = (i < DIM * DIM) ? g_wt1_lo : g_wt2_lo;
    int j = i & (DIM * DIM - 1);
    int nIdx = j >> 7;
    int k = j & 127;
    float w = W[k * DIM + nIdx];
    __nv_bfloat16 h = __float2bfloat16(w);
    H[j] = h;
    L[j] = __float2bfloat16(w - __bfloat162float(h));
}

// ---------------------------------------------------------------------------
// Tensor-core GEMM via mma.sync (family-level PTX). bf16 hi/lo 3-pass.
// CTA: 256 rows x 128 cols; 8 warps x 32 rows.
// ---------------------------------------------------------------------------
#define PADB 272
#define SM_AH 0
#define SM_AL 69632
#define SM_BH 139264
#define SM_BL 174080
#define SMEM_GEMM_BYTES 208896

__global__ void __launch_bounds__(256, 1)
gemm_mma_kernel(const float* __restrict__ A,
                const __nv_bfloat16* __restrict__ Bh,
                const __nv_bfloat16* __restrict__ Bl,
                const float* __restrict__ bias,
                float* __restrict__ C, int n, int relu) {
    extern __shared__ char smem[];
    uint32_t sb = smem_u32(smem);
    int tid = threadIdx.x, wid = tid >> 5, lane = tid & 31;
    int row0 = blockIdx.x * 256;

    const float4* A4 = (const float4*)A;
#pragma unroll
    for (int i = 0; i < 32; i++) {
        int idx = tid + 256 * i;
        int r = idx >> 5, c4 = idx & 31;
        int gr = row0 + r;
        float4 v = (gr < n) ? A4[(size_t)gr * 32 + c4]
                            : make_float4(0.f, 0.f, 0.f, 0.f);
        __nv_bfloat16 h0 = __float2bfloat16(v.x);
        __nv_bfloat16 h1 = __float2bfloat16(v.y);
        __nv_bfloat16 h2 = __float2bfloat16(v.z);
        __nv_bfloat16 h3 = __float2bfloat16(v.w);
        __nv_bfloat162 ph0 = __halves2bfloat162(h0, h1);
        __nv_bfloat162 ph1 = __halves2bfloat162(h2, h3);
        __nv_bfloat162 pl0 = __halves2bfloat162(
            __float2bfloat16(v.x - __bfloat162float(h0)),
            __float2bfloat16(v.y - __bfloat162float(h1)));
        __nv_bfloat162 pl1 = __halves2bfloat162(
            __float2bfloat16(v.z - __bfloat162float(h2)),
            __float2bfloat16(v.w - __bfloat162float(h3)));
        char* ph = smem + SM_AH + r * PADB + c4 * 8;
        char* pl = smem + SM_AL + r * PADB + c4 * 8;
        *(uint2*)ph = make_uint2(*reinterpret_cast<uint32_t*>(&ph0),
                                 *reinterpret_cast<uint32_t*>(&ph1));
        *(uint2*)pl = make_uint2(*reinterpret_cast<uint32_t*>(&pl0),
                                 *reinterpret_cast<uint32_t*>(&pl1));
    }

    const uint2* bh2 = (const uint2*)Bh;
    const uint2* bl2 = (const uint2*)Bl;
#pragma unroll
    for (int i = 0; i < 16; i++) {
        int idx = tid + 256 * i;
        int r = idx >> 5, c4 = idx & 31;
        *(uint2*)(smem + SM_BH + r * PADB + c4 * 8) = bh2[idx];
        *(uint2*)(smem + SM_BL + r * PADB + c4 * 8) = bl2[idx];
    }
    __syncthreads();

    int lr = lane & 7;
    int li = lane >> 3;
    uint32_t aoff = (uint32_t)((wid * 32 + lr + (li & 1) * 8) * PADB +
                               ((li >> 1) * 8) * 2);
    uint32_t boff = (uint32_t)((lr + (li >> 1) * 8) * PADB + ((li & 1) * 8) * 2);

    float acc[2][16][4];
#pragma unroll
    for (int mt = 0; mt < 2; mt++)
#pragma unroll
        for (int nt = 0; nt < 16; nt++)
#pragma unroll
            for (int q = 0; q < 4; q++) acc[mt][nt][q] = 0.0f;

    for (int ks = 0; ks < 8; ks++) {
        uint32_t kadd = ks * 32;
        uint32_t ah[2][4], al[2][4];
        ldsm4(ah[0], sb + SM_AH + aoff + kadd);
        ldsm4(ah[1], sb + SM_AH + aoff + 16 * PADB + kadd);
        ldsm4(al[0], sb + SM_AL + aoff + kadd);
        ldsm4(al[1], sb + SM_AL + aoff + 16 * PADB + kadd);
#pragma unroll
        for (int ng = 0; ng < 8; ng++) {
            uint32_t nadd = ng * 16 * PADB;
            uint32_t bh[4], bl[4];
            ldsm4(bh, sb + SM_BH + boff + nadd + kadd);
            ldsm4(bl, sb + SM_BL + boff + nadd + kadd);
#pragma unroll
            for (int mt = 0; mt < 2; mt++) {
                mma_bf16(acc[mt][2 * ng],     ah[mt], bh[0], bh[1]);
                mma_bf16(acc[mt][2 * ng],     ah[mt], bl[0], bl[1]);
                mma_bf16(acc[mt][2 * ng],     al[mt], bh[0], bh[1]);
                mma_bf16(acc[mt][2 * ng + 1], ah[mt], bh[2], bh[3]);
                mma_bf16(acc[mt][2 * ng + 1], ah[mt], bl[2], bl[3]);
                mma_bf16(acc[mt][2 * ng + 1], al[mt], bh[2], bh[3]);
            }
        }
    }

#pragma unroll
    for (int nt = 0; nt < 16; nt++) {
        int col = nt * 8 + (lane & 3) * 2;
        float2 bv = *(const float2*)(bias + col);
#pragma unroll
        for (int mt = 0; mt < 2; mt++) {
            int r0 = row0 + wid * 32 + mt * 16 + (lane >> 2);
            float* a = acc[mt][nt];
            float v0 = a[0] + bv.x, v1 = a[1] + bv.y;
            float v2 = a[2] + bv.x, v3 = a[3] + bv.y;
            if (relu) {
                v0 = fmaxf(v0, 0.f); v1 = fmaxf(v1, 0.f);
                v2 = fmaxf(v2, 0.f); v3 = fmaxf(v3, 0.f);
            }
            if (r0 < n)     *(float2*)(C + (size_t)r0 * 128 + col) = make_float2(v0, v1);
            if (r0 + 8 < n) *(float2*)(C + (size_t)(r0 + 8) * 128 + col) = make_float2(v2, v3);
        }
    }
}

// ---------------------------------------------------------------------------
extern "C" void kernel_launch(void* const* d_in, const int* in_sizes, int n_in,
                              void* d_out, int out_size) {
    const float* x   = (const float*)d_in[0];
    const void*  ei  = d_in[1];
    const float* W1  = (const float*)d_in[2];
    const float* b1  = (const float*)d_in[3];
    const float* W2  = (const float*)d_in[4];
    const float* b2  = (const float*)d_in[5];
    const float* eps = (const float*)d_in[6];

    int N = in_sizes[0] / DIM;
    int E = in_sizes[1] / 2;

    float* agg_ptr = nullptr;
    float* h1_ptr  = nullptr;
    __nv_bfloat16 *wt1h, *wt1l, *wt2h, *wt2l;
    cudaGetSymbolAddress((void**)&agg_ptr, g_agg);
    cudaGetSymbolAddress((void**)&h1_ptr,  g_h1);
    cudaGetSymbolAddress((void**)&wt1h, g_wt1_hi);
    cudaGetSymbolAddress((void**)&wt1l, g_wt1_lo);
    cudaGetSymbolAddress((void**)&wt2h, g_wt2_hi);
    cudaGetSymbolAddress((void**)&wt2l, g_wt2_lo);

    detect_kernel<<<1, 32>>>((const unsigned int*)ei);
    prep_w_kernel<<<(2 * DIM * DIM + 255) / 256, 256>>>(W1, W2);

    if (E <= EDGES_MAX && N <= NNODES) {
        // CSR build + ordered aggregation
        zero_cnt_kernel<<<(N + 255) / 256, 256>>>(N);
        hist_kernel<<<(E + 255) / 256, 256>>>(ei, E);
        int nb_scan = (N + SCAN_BLK - 1) / SCAN_BLK;
        scan1_kernel<<<nb_scan, 512>>>(N);
        scan2_kernel<<<1, 32>>>(nb_scan);
        scan3_kernel<<<(N + 255) / 256, 256>>>(N, E);
        reorder_kernel<<<(E + 255) / 256, 256>>>(ei, E);
        agg_kernel<<<(N * 32 + 255) / 256, 256>>>((const float4*)x, eps, N);
    } else {
        int n4 = N * (DIM / 4);
        init_kernel<<<(n4 + 255) / 256, 256>>>((const float4*)x, eps, n4);
        long long tot = (long long)E * 32;
        scatter_kernel<<<(int)((tot + 255) / 256), 256>>>((const float4*)x, ei, E);
    }

    cudaFuncSetAttribute(gemm_mma_kernel,
                         cudaFuncAttributeMaxDynamicSharedMemorySize,
                         SMEM_GEMM_BYTES);
    int nb = (N + 255) / 256;
    gemm_mma_kernel<<<nb, 256, SMEM_GEMM_BYTES>>>(agg_ptr, wt1h, wt1l, b1,
                                                  h1_ptr, N, 1);
    gemm_mma_kernel<<<nb, 256, SMEM_GEMM_BYTES>>>(h1_ptr, wt2h, wt2l, b2,
                                                  (float*)d_out, N, 0);
}